// round 14
// baseline (speedup 1.0000x reference)
#include <cuda_runtime.h>
#include <cuda_bf16.h>
#include <math.h>
#include <stdint.h>

#define IN_DIM   256
#define OUT_DIM  256
#define BATCH    4096
#define NROWS    12
#define KSEG     (IN_DIM * NROWS)      // 3072 dense K per term
#define KA       (2 * KSEG)            // A_cat row: hi | lo           = 6144
#define KB       (3 * KSEG)            // B_cat row: Whi | Wlo | Whi   = 9216
#define KC       192                   // K per chunk
#define NCH      (KB / KC)             // 48
#define CSEG     (KSEG / KC)           // 16

// Scratch (static __device__ — no allocation).
__device__ __nv_bfloat16 g_A[(size_t)BATCH * KA];    // ~50 MB (L2-resident)
__device__ __nv_bfloat16 g_B[(size_t)OUT_DIM * KB];  // ~4.7 MB

// ===========================================================================
// Kernel 1: A_cat — dense 12-wide basis/silu per (b,i), split hi|lo bf16.
// Branchless (SEL-based) dense vector: no dynamically-indexed local array.
// Smem-staged, coalesced uint4 stores.
// ===========================================================================
__global__ void __launch_bounds__(256) prep_a(const float* __restrict__ x) {
    __shared__ uint32_t st[3072];                 // 12 KB row image for batch b
    int b = blockIdx.x;
    int i = threadIdx.x;
    float xv = x[(size_t)b * IN_DIM + i];
    float t8 = xv * 8.0f;
    float fl = floorf(t8);
    float u  = t8 - fl;
    int k0l = min(max((int)fl, 0), 7);
    const float inv6 = 1.0f / 6.0f;
    float u2 = u * u, u3 = u2 * u;
    float omu = 1.0f - u;
    float c0 = omu * omu * omu * inv6;
    float c1 = (3.0f * u3 - 6.0f * u2 + 4.0f) * inv6;
    float c2 = (-3.0f * u3 + 3.0f * u2 + 3.0f * u + 1.0f) * inv6;
    float c3 = u3 * inv6;
    float sl = xv / (1.0f + __expf(-xv));         // silu (fast exp; err ~2^-17)

    unsigned short hb[NROWS], lb[NROWS];
#pragma unroll
    for (int kk = 0; kk < NROWS; kk++) {
        float v = 0.0f;                           // branchless select (no lmem)
        v = (kk == k0l)     ? c0 : v;
        v = (kk == k0l + 1) ? c1 : v;
        v = (kk == k0l + 2) ? c2 : v;
        v = (kk == k0l + 3) ? c3 : v;
        if (kk == 11) v = sl;                     // k0l+3 <= 10, no overlap
        __nv_bfloat16 h = __float2bfloat16(v);
        float lo = v - __bfloat162float(h);
        __nv_bfloat16 l = __float2bfloat16(lo);
        hb[kk] = *reinterpret_cast<unsigned short*>(&h);
        lb[kk] = *reinterpret_cast<unsigned short*>(&l);
    }
#pragma unroll
    for (int j = 0; j < 6; j++) {
        st[i * 6 + j]        = (uint32_t)hb[2 * j] | ((uint32_t)hb[2 * j + 1] << 16);
        st[1536 + i * 6 + j] = (uint32_t)lb[2 * j] | ((uint32_t)lb[2 * j + 1] << 16);
    }
    __syncthreads();

    const uint4* s4 = reinterpret_cast<const uint4*>(st);
    uint4* g4 = reinterpret_cast<uint4*>(g_A) + (size_t)b * 768;
#pragma unroll
    for (int p = 0; p < 3; p++)
        g4[p * 256 + i] = s4[p * 256 + i];
}

// ===========================================================================
// Kernel 2: B_cat — W[i][kk][o] = sc*cp (row 11 = sc), split Whi|Wlo|Whi.
// ===========================================================================
__global__ void prep_b(const float* __restrict__ cp, const float* __restrict__ sc) {
    int o = blockIdx.x;
    int i = threadIdx.x;
    float s = sc[i * OUT_DIM + o];
    const float* cpp = cp + (size_t)(i * OUT_DIM + o) * 19;
    __nv_bfloat16* pb = g_B + (size_t)o * KB + i * NROWS;
#pragma unroll
    for (int kk = 0; kk < NROWS; kk++) {
        float w = (kk < 11) ? s * cpp[kk + 8] : s;
        __nv_bfloat16 h = __float2bfloat16(w);
        float lo = w - __bfloat162float(h);
        pb[kk]            = h;
        pb[KSEG + kk]     = __float2bfloat16(lo);
        pb[2 * KSEG + kk] = h;
    }
}

// ===========================================================================
// PTX helpers (sm_80-class only: cp.async, ldmatrix, mma.sync — no tcgen05)
// ===========================================================================
__device__ __forceinline__ uint32_t smem_u32(const void* p) {
    uint32_t a;
    asm("{ .reg .u64 t; cvta.to.shared.u64 t, %1; cvt.u32.u64 %0, t; }"
        : "=r"(a) : "l"(p));
    return a;
}
__device__ __forceinline__ void cp16(uint32_t dst, const void* src) {
    asm volatile("cp.async.cg.shared.global [%0], [%1], 16;"
                 :: "r"(dst), "l"(src) : "memory");
}
__device__ __forceinline__ void cp_commit() {
    asm volatile("cp.async.commit_group;" ::: "memory");
}
template <int N>
__device__ __forceinline__ void cp_wait() {
    asm volatile("cp.async.wait_group %0;" :: "n"(N) : "memory");
}
__device__ __forceinline__ void ldm_x4(uint32_t* r, uint32_t addr) {
    asm volatile("ldmatrix.sync.aligned.m8n8.x4.shared.b16 {%0,%1,%2,%3}, [%4];"
                 : "=r"(r[0]), "=r"(r[1]), "=r"(r[2]), "=r"(r[3]) : "r"(addr));
}
__device__ __forceinline__ void mma16816(float* d, const uint32_t* a,
                                         const uint32_t* b) {
    asm volatile(
        "mma.sync.aligned.m16n8k16.row.col.f32.bf16.bf16.f32 "
        "{%0,%1,%2,%3}, {%4,%5,%6,%7}, {%8,%9}, {%0,%1,%2,%3};"
        : "+f"(d[0]), "+f"(d[1]), "+f"(d[2]), "+f"(d[3])
        : "r"(a[0]), "r"(a[1]), "r"(a[2]), "r"(a[3]), "r"(b[0]), "r"(b[1]));
}

// ===========================================================================
// Kernel 3: HMMA GEMM. out[4096,256] = A_cat · B_cat^T.
// CTA: M=128, N=64. grid = 32 btiles x 4 ntiles = 128 CTAs.
// 512 threads = 16 warps (4 per SMSP for latency hiding), warps 4(M)x4(N),
// warp tile 32x16 (2 mt x 2 nt, 3 LDSM per k-step).
// KC=192 (12 k-steps per barrier), 3-stage cp.async, ONE sync/chunk,
// fragment double-buffering across k-steps.
// Smem rows 400B stride (r*400 mod 128 = r*16 -> conflict-free ldmatrix).
// ===========================================================================
#define ROWB  400                       // bytes per padded smem row (384 data)
#define ASTG  (128 * ROWB)              // 51200
#define BSTG  (64 * ROWB)               // 25600
#define STG_B (ASTG + BSTG)             // 76800 per stage
#define SMTOT (3 * STG_B)               // 230400 (fits 227KB opt-in)
#define AUN   (KC / 8)                  // 24 16B-units per A/B row

__global__ void __launch_bounds__(512) kan_mma(float* __restrict__ out) {
    extern __shared__ char smem[];
    uint32_t sbase = smem_u32(smem);
    uint32_t sA[3], sB[3];
#pragma unroll
    for (int s = 0; s < 3; s++) {
        sA[s] = sbase + s * STG_B;
        sB[s] = sbase + s * STG_B + ASTG;
    }

    int tid  = threadIdx.x;
    int wid  = tid >> 5;
    int lane = tid & 31;
    int btile = blockIdx.x >> 2;          // 0..31
    int ntile = blockIdx.x & 3;           // 0..3
    int warp_m = wid >> 2;                // 0..3 (32 M-rows each)
    int warp_n = wid & 3;                 // 0..3 (16 N-rows each)

    // ---- cp.async per-thread mapping ----
    // A tile: 128 rows x 24 units = 3072 units -> 6 per thread (512 thr)
    // B tile:  64 rows x 24 units = 1536 units -> 3 per thread
    const __nv_bfloat16* gA[6];
    uint32_t dA[6];
#pragma unroll
    for (int j = 0; j < 6; j++) {
        int w = tid + 512 * j;
        int r = w / AUN, cu = w % AUN;
        gA[j] = g_A + (size_t)(btile * 128 + r) * KA + cu * 8;
        dA[j] = r * ROWB + cu * 16;
    }
    const __nv_bfloat16* gB[3];
    uint32_t dB[3];
#pragma unroll
    for (int j = 0; j < 3; j++) {
        int w = tid + 512 * j;
        int r = w / AUN, cu = w % AUN;
        gB[j] = g_B + (size_t)(ntile * 64 + r) * KB + cu * 8;
        dB[j] = r * ROWB + cu * 16;
    }

    // ---- ldmatrix per-lane base offsets ----
    // A x4 per mt: row = warp_m*32 + mt*16 + (lane&7) + 8*((lane>>3)&1), khalf=(lane>>4)
    uint32_t a_off[2];
#pragma unroll
    for (int mt = 0; mt < 2; mt++) {
        int r = warp_m * 32 + mt * 16 + (lane & 7) + 8 * ((lane >> 3) & 1);
        a_off[mt] = r * ROWB + (lane >> 4) * 16;
    }
    // B x4 covers warp's 16 n-rows, both k-halves:
    // row = warp_n*16 + 8*((lane>>4)&1) + (lane&7), khalf = (lane>>3)&1
    // -> bfr = {n8t0k0, n8t0k1, n8t1k0, n8t1k1}
    uint32_t b_off;
    {
        int r = warp_n * 16 + ((lane >> 4) & 1) * 8 + (lane & 7);
        b_off = r * ROWB + ((lane >> 3) & 1) * 16;
    }

    float acc[2][2][4];
#pragma unroll
    for (int mt = 0; mt < 2; mt++)
#pragma unroll
        for (int nt = 0; nt < 2; nt++)
#pragma unroll
            for (int q = 0; q < 4; q++) acc[mt][nt][q] = 0.0f;

#define ISSUE(c, s) do {                                                        \
        int _c = (c);                                                           \
        int _seg = _c / CSEG;                                                   \
        int _aoff = ((_seg == 2) ? KSEG : 0) + (_c - _seg * CSEG) * KC;         \
        int _boff = _c * KC;                                                    \
        _Pragma("unroll")                                                       \
        for (int j = 0; j < 6; j++)                                             \
            cp16(sA[s] + dA[j], gA[j] + _aoff);                                 \
        _Pragma("unroll")                                                       \
        for (int j = 0; j < 3; j++)                                             \
            cp16(sB[s] + dB[j], gB[j] + _boff);                                 \
        cp_commit();                                                            \
    } while (0)

#define LOADF(buf, s, ks) do {                                                  \
        uint32_t _kb = (ks) * 32;                                               \
        _Pragma("unroll")                                                       \
        for (int mt = 0; mt < 2; mt++)                                          \
            ldm_x4(afr[buf][mt], sA[s] + a_off[mt] + _kb);                      \
        ldm_x4(bfr[buf], sB[s] + b_off + _kb);                                  \
    } while (0)

#define MMAS(buf) do {                                                          \
        _Pragma("unroll")                                                       \
        for (int mt = 0; mt < 2; mt++) {                                        \
            _Pragma("unroll")                                                   \
            for (int nt = 0; nt < 2; nt++) {                                    \
                uint32_t bb[2] = { bfr[buf][nt * 2 + 0], bfr[buf][nt * 2 + 1] }; \
                mma16816(acc[mt][nt], afr[buf][mt], bb);                        \
            }                                                                   \
        }                                                                       \
    } while (0)

    // prologue: 2 chunks in flight
    ISSUE(0, 0);
    ISSUE(1, 1);

    for (int c = 0; c < NCH; c++) {
        int s = c % 3;
        if (c + 1 < NCH) cp_wait<1>(); else cp_wait<0>();
        __syncthreads();

        if (c + 2 < NCH) ISSUE(c + 2, (c + 2) % 3);   // stage freed at iter c-1

        uint32_t afr[2][2][4], bfr[2][4];
        LOADF(0, s, 0);
#pragma unroll
        for (int ks = 0; ks < 12; ks++) {
            if (ks < 11) LOADF((ks + 1) & 1, s, ks + 1);
            MMAS(ks & 1);
        }
    }

    // ---- epilogue ----
    int mg = btile * 128 + warp_m * 32 + (lane >> 2);
    int ng = ntile * 64 + warp_n * 16 + (lane & 3) * 2;
#pragma unroll
    for (int mt = 0; mt < 2; mt++) {
#pragma unroll
        for (int nt = 0; nt < 2; nt++) {
            int m0 = mg + mt * 16;
            int n0 = ng + nt * 8;
            float2 v0 = make_float2(acc[mt][nt][0], acc[mt][nt][1]);
            float2 v1 = make_float2(acc[mt][nt][2], acc[mt][nt][3]);
            *reinterpret_cast<float2*>(out + (size_t)m0 * OUT_DIM + n0) = v0;
            *reinterpret_cast<float2*>(out + (size_t)(m0 + 8) * OUT_DIM + n0) = v1;
        }
    }
#undef MMAS
#undef LOADF
#undef ISSUE
}

// ---------------------------------------------------------------------------
extern "C" void kernel_launch(void* const* d_in, const int* in_sizes, int n_in,
                              void* d_out, int out_size) {
    const float* x  = (const float*)d_in[0];   // [4096, 256]
    const float* cp = (const float*)d_in[1];   // [256, 256, 19]
    const float* sc = (const float*)d_in[2];   // [256, 256]
    float* out = (float*)d_out;                // [4096, 256]

    cudaFuncSetAttribute(kan_mma, cudaFuncAttributeMaxDynamicSharedMemorySize,
                         SMTOT);

    prep_a<<<BATCH,   IN_DIM>>>(x);
    prep_b<<<OUT_DIM, IN_DIM>>>(cp, sc);
    kan_mma<<<128, 512, SMTOT>>>(out);
}

// round 15
// speedup vs baseline: 1.1458x; 1.1458x over previous
#include <cuda_runtime.h>
#include <cuda_bf16.h>
#include <math.h>
#include <stdint.h>

#define IN_DIM   256
#define OUT_DIM  256
#define BATCH    4096
#define NROWS    12
#define KSEG     (IN_DIM * NROWS)      // 3072 dense K per term
#define KA       (2 * KSEG)            // A_cat row: hi | lo           = 6144
#define KB       (3 * KSEG)            // B_cat row: Whi | Wlo | Whi   = 9216
#define KC       64                    // K per chunk
#define NCHG     (KB / KC)             // 144 global chunks
#define NCHL     (NCHG / 2)            // 72 per K-half CTA
#define CSEG     (KSEG / KC)           // 48

// Scratch (static __device__ — no allocation).
__device__ __nv_bfloat16 g_A[(size_t)BATCH * KA];    // ~50 MB (L2-resident)
__device__ __nv_bfloat16 g_B[(size_t)OUT_DIM * KB];  // ~4.7 MB
__device__ float g_part[(size_t)BATCH * OUT_DIM];    // 4 MB partial (K-half 1)

// ===========================================================================
// Kernel 1: A_cat — dense 12-wide basis/silu per (b,i), split hi|lo bf16.
// (R13 version — measured 11.9 us.)
// ===========================================================================
__global__ void __launch_bounds__(256) prep_a(const float* __restrict__ x) {
    __shared__ uint32_t st[3072];                 // 12 KB row image for batch b
    int b = blockIdx.x;
    int i = threadIdx.x;
    float xv = x[(size_t)b * IN_DIM + i];
    float t8 = xv * 8.0f;
    float fl = floorf(t8);
    float u  = t8 - fl;
    int k0l = min(max((int)fl, 0), 7);
    const float inv6 = 1.0f / 6.0f;
    float u2 = u * u, u3 = u2 * u;
    float omu = 1.0f - u;
    float d[NROWS];
#pragma unroll
    for (int kk = 0; kk < NROWS; kk++) d[kk] = 0.0f;
    d[k0l + 0] = omu * omu * omu * inv6;
    d[k0l + 1] = (3.0f * u3 - 6.0f * u2 + 4.0f) * inv6;
    d[k0l + 2] = (-3.0f * u3 + 3.0f * u2 + 3.0f * u + 1.0f) * inv6;
    d[k0l + 3] = u3 * inv6;
    d[11]      = xv / (1.0f + __expf(-xv));       // silu (fast exp; err ~2^-17)

    unsigned short hb[NROWS], lb[NROWS];
#pragma unroll
    for (int kk = 0; kk < NROWS; kk++) {
        float v = d[kk];
        __nv_bfloat16 h = __float2bfloat16(v);
        float lo = v - __bfloat162float(h);
        __nv_bfloat16 l = __float2bfloat16(lo);
        hb[kk] = *reinterpret_cast<unsigned short*>(&h);
        lb[kk] = *reinterpret_cast<unsigned short*>(&l);
    }
#pragma unroll
    for (int j = 0; j < 6; j++) {
        st[i * 6 + j]        = (uint32_t)hb[2 * j] | ((uint32_t)hb[2 * j + 1] << 16);
        st[1536 + i * 6 + j] = (uint32_t)lb[2 * j] | ((uint32_t)lb[2 * j + 1] << 16);
    }
    __syncthreads();

    const uint4* s4 = reinterpret_cast<const uint4*>(st);
    uint4* g4 = reinterpret_cast<uint4*>(g_A) + (size_t)b * 768;
#pragma unroll
    for (int p = 0; p < 3; p++)
        g4[p * 256 + i] = s4[p * 256 + i];
}

// ===========================================================================
// Kernel 2: B_cat — W[i][kk][o] = sc*cp (row 11 = sc), split Whi|Wlo|Whi.
// ===========================================================================
__global__ void prep_b(const float* __restrict__ cp, const float* __restrict__ sc) {
    int o = blockIdx.x;
    int i = threadIdx.x;
    float s = sc[i * OUT_DIM + o];
    const float* cpp = cp + (size_t)(i * OUT_DIM + o) * 19;
    __nv_bfloat16* pb = g_B + (size_t)o * KB + i * NROWS;
#pragma unroll
    for (int kk = 0; kk < NROWS; kk++) {
        float w = (kk < 11) ? s * cpp[kk + 8] : s;
        __nv_bfloat16 h = __float2bfloat16(w);
        float lo = w - __bfloat162float(h);
        pb[kk]            = h;
        pb[KSEG + kk]     = __float2bfloat16(lo);
        pb[2 * KSEG + kk] = h;
    }
}

// ===========================================================================
// PTX helpers (sm_80-class only: cp.async, ldmatrix, mma.sync — no tcgen05)
// ===========================================================================
__device__ __forceinline__ uint32_t smem_u32(const void* p) {
    uint32_t a;
    asm("{ .reg .u64 t; cvta.to.shared.u64 t, %1; cvt.u32.u64 %0, t; }"
        : "=r"(a) : "l"(p));
    return a;
}
__device__ __forceinline__ void cp16(uint32_t dst, const void* src) {
    asm volatile("cp.async.cg.shared.global [%0], [%1], 16;"
                 :: "r"(dst), "l"(src) : "memory");
}
__device__ __forceinline__ void cp_commit() {
    asm volatile("cp.async.commit_group;" ::: "memory");
}
template <int N>
__device__ __forceinline__ void cp_wait() {
    asm volatile("cp.async.wait_group %0;" :: "n"(N) : "memory");
}
__device__ __forceinline__ void ldm_x4(uint32_t* r, uint32_t addr) {
    asm volatile("ldmatrix.sync.aligned.m8n8.x4.shared.b16 {%0,%1,%2,%3}, [%4];"
                 : "=r"(r[0]), "=r"(r[1]), "=r"(r[2]), "=r"(r[3]) : "r"(addr));
}
__device__ __forceinline__ void mma16816(float* d, const uint32_t* a,
                                         const uint32_t* b) {
    asm volatile(
        "mma.sync.aligned.m16n8k16.row.col.f32.bf16.bf16.f32 "
        "{%0,%1,%2,%3}, {%4,%5,%6,%7}, {%8,%9}, {%0,%1,%2,%3};"
        : "+f"(d[0]), "+f"(d[1]), "+f"(d[2]), "+f"(d[3])
        : "r"(a[0]), "r"(a[1]), "r"(a[2]), "r"(a[3]), "r"(b[0]), "r"(b[1]));
}

// ===========================================================================
// Kernel 3: HMMA GEMM, split-K(2). out[4096,256] = A_cat · B_cat^T.
// CTA: M=128, N=64, K-half 4608. grid = 32 btile x 4 ntile x 2 khalf = 256
// CTAs, 256 threads, 8 warps 4(M)x2(N), warp tile 32x32 (R13 geometry).
// KC=64 (4 k-steps), ROWB=144, FOUR cp.async stages (110.6 KB total smem ->
// TWO CTAs co-resident per SM: 148 SMs busy, 4 warps/SMSP).
// khalf 0 -> out, khalf 1 -> g_part; combine kernel adds.
// ===========================================================================
#define ROWB  144                       // bytes per padded smem row (128 data)
#define ASTG  (128 * ROWB)              // 18432
#define BSTG  (64 * ROWB)               // 9216
#define STG_B (ASTG + BSTG)             // 27648 per stage
#define NSTG  4
#define SMTOT (NSTG * STG_B)            // 110592 (x2 CTAs = 221 KB < 227 KB)

__global__ void __launch_bounds__(256) kan_mma(float* __restrict__ out) {
    extern __shared__ char smem[];
    uint32_t sbase = smem_u32(smem);
    uint32_t sA[NSTG], sB[NSTG];
#pragma unroll
    for (int s = 0; s < NSTG; s++) {
        sA[s] = sbase + s * STG_B;
        sB[s] = sbase + s * STG_B + ASTG;
    }

    int tid  = threadIdx.x;
    int wid  = tid >> 5;
    int lane = tid & 31;
    int btile  = blockIdx.x >> 3;         // 0..31
    int ntile  = (blockIdx.x >> 1) & 3;   // 0..3
    int khalf  = blockIdx.x & 1;          // 0..1
    int cbase  = khalf * NCHL;            // global chunk offset
    int warp_m = wid >> 1;                // 0..3
    int warp_n = wid & 1;                 // 0..1

    // ---- cp.async per-thread mapping (A: 4 ops, B: 2 ops per chunk) ----
    int u    = tid & 7;                   // 16B unit in 128B row
    int row0 = tid >> 3;                  // 0..31
    const __nv_bfloat16* gA[4];
    uint32_t dA[4];
#pragma unroll
    for (int j = 0; j < 4; j++) {
        int r = row0 + 32 * j;
        gA[j] = g_A + (size_t)(btile * 128 + r) * KA + u * 8;
        dA[j] = r * ROWB + u * 16;
    }
    const __nv_bfloat16* gB[2];
    uint32_t dB[2];
#pragma unroll
    for (int j = 0; j < 2; j++) {
        int r = row0 + 32 * j;
        gB[j] = g_B + (size_t)(ntile * 64 + r) * KB + u * 8;
        dB[j] = r * ROWB + u * 16;
    }

    // ---- ldmatrix per-lane base offsets (R13 geometry) ----
    uint32_t a_off[2];
#pragma unroll
    for (int mt = 0; mt < 2; mt++) {
        int r = warp_m * 32 + mt * 16 + (lane & 7) + 8 * ((lane >> 3) & 1);
        a_off[mt] = r * ROWB + (lane >> 4) * 16;
    }
    uint32_t b_off[2];
#pragma unroll
    for (int np = 0; np < 2; np++) {
        int r = warp_n * 32 + np * 16 + ((lane >> 4) & 1) * 8 + (lane & 7);
        b_off[np] = r * ROWB + ((lane >> 3) & 1) * 16;
    }

    float acc[2][4][4];
#pragma unroll
    for (int mt = 0; mt < 2; mt++)
#pragma unroll
        for (int nt = 0; nt < 4; nt++)
#pragma unroll
            for (int q = 0; q < 4; q++) acc[mt][nt][q] = 0.0f;

#define ISSUE(cl, s) do {                                                       \
        int _g = cbase + (cl);                    /* global chunk */            \
        int _seg = _g / CSEG;                                                   \
        int _aoff = ((_seg == 2) ? KSEG : 0) + (_g - _seg * CSEG) * KC;         \
        int _boff = _g * KC;                                                    \
        _Pragma("unroll")                                                       \
        for (int j = 0; j < 4; j++)                                             \
            cp16(sA[s] + dA[j], gA[j] + _aoff);                                 \
        _Pragma("unroll")                                                       \
        for (int j = 0; j < 2; j++)                                             \
            cp16(sB[s] + dB[j], gB[j] + _boff);                                 \
        cp_commit();                                                            \
    } while (0)

#define LOADF(buf, s, ks) do {                                                  \
        uint32_t _kb = (ks) * 32;                                               \
        _Pragma("unroll")                                                       \
        for (int mt = 0; mt < 2; mt++)                                          \
            ldm_x4(afr[buf][mt], sA[s] + a_off[mt] + _kb);                      \
        _Pragma("unroll")                                                       \
        for (int np = 0; np < 2; np++)                                          \
            ldm_x4(bfr[buf][np], sB[s] + b_off[np] + _kb);                      \
    } while (0)

#define MMAS(buf) do {                                                          \
        _Pragma("unroll")                                                       \
        for (int mt = 0; mt < 2; mt++) {                                        \
            _Pragma("unroll")                                                   \
            for (int nt = 0; nt < 4; nt++) {                                    \
                uint32_t bb[2] = { bfr[buf][nt >> 1][(nt & 1) * 2 + 0],         \
                                   bfr[buf][nt >> 1][(nt & 1) * 2 + 1] };       \
                mma16816(acc[mt][nt], afr[buf][mt], bb);                        \
            }                                                                   \
        }                                                                       \
    } while (0)

    // prologue: 3 chunks in flight
    ISSUE(0, 0);
    ISSUE(1, 1);
    ISSUE(2, 2);

    for (int c = 0; c < NCHL; c++) {
        int s = c % NSTG;
        if (c + 2 < NCHL)      cp_wait<2>();
        else if (c + 1 < NCHL) cp_wait<1>();
        else                   cp_wait<0>();
        __syncthreads();

        if (c + 3 < NCHL) ISSUE(c + 3, (c + 3) % NSTG);  // stage freed at c-1

        uint32_t afr[2][2][4], bfr[2][2][4];
        LOADF(0, s, 0);
#pragma unroll
        for (int ks = 0; ks < 4; ks++) {
            if (ks < 3) LOADF((ks + 1) & 1, s, ks + 1);
            MMAS(ks & 1);
        }
    }

    // ---- epilogue: khalf 0 -> out, khalf 1 -> g_part ----
    float* dst = khalf ? g_part : out;
    int mg = btile * 128 + warp_m * 32 + (lane >> 2);
    int ng = ntile * 64 + warp_n * 32 + (lane & 3) * 2;
#pragma unroll
    for (int mt = 0; mt < 2; mt++) {
#pragma unroll
        for (int nt = 0; nt < 4; nt++) {
            int m0 = mg + mt * 16;
            int n0 = ng + nt * 8;
            float2 v0 = make_float2(acc[mt][nt][0], acc[mt][nt][1]);
            float2 v1 = make_float2(acc[mt][nt][2], acc[mt][nt][3]);
            *reinterpret_cast<float2*>(dst + (size_t)m0 * OUT_DIM + n0) = v0;
            *reinterpret_cast<float2*>(dst + (size_t)(m0 + 8) * OUT_DIM + n0) = v1;
        }
    }
#undef MMAS
#undef LOADF
#undef ISSUE
}

// ===========================================================================
// Kernel 4: combine — out += g_part (float4, fully coalesced).
// ===========================================================================
__global__ void __launch_bounds__(256) combine(float* __restrict__ out) {
    int idx = blockIdx.x * 256 + threadIdx.x;     // 1024 blocks x 256 = 262144
    float4* o4 = reinterpret_cast<float4*>(out);
    const float4* p4 = reinterpret_cast<const float4*>(g_part);
    float4 a = o4[idx], b = p4[idx];
    a.x += b.x; a.y += b.y; a.z += b.z; a.w += b.w;
    o4[idx] = a;
}

// ---------------------------------------------------------------------------
extern "C" void kernel_launch(void* const* d_in, const int* in_sizes, int n_in,
                              void* d_out, int out_size) {
    const float* x  = (const float*)d_in[0];   // [4096, 256]
    const float* cp = (const float*)d_in[1];   // [256, 256, 19]
    const float* sc = (const float*)d_in[2];   // [256, 256]
    float* out = (float*)d_out;                // [4096, 256]

    cudaFuncSetAttribute(kan_mma, cudaFuncAttributeMaxDynamicSharedMemorySize,
                         SMTOT);

    prep_a<<<BATCH,   IN_DIM>>>(x);
    prep_b<<<OUT_DIM, IN_DIM>>>(cp, sc);
    kan_mma<<<256, 256, SMTOT>>>(out);
    combine<<<(BATCH * OUT_DIM) / 4 / 256, 256>>>(out);
}

// round 16
// speedup vs baseline: 1.1629x; 1.0149x over previous
#include <cuda_runtime.h>
#include <cuda_bf16.h>
#include <math.h>
#include <stdint.h>

#define IN_DIM   256
#define OUT_DIM  256
#define BATCH    4096
#define NROWS    12
#define KSEG     (IN_DIM * NROWS)      // 3072 dense K per term
#define KA       (2 * KSEG)            // A_cat row: hi | lo           = 6144
#define KB       (3 * KSEG)            // B_cat row: Whi | Wlo | Whi   = 9216
#define KC       64                    // K per chunk
#define NCHG     (KB / KC)             // 144 global chunks
#define NCHL     (NCHG / 2)            // 72 per K-half CTA
#define CSEG     (KSEG / KC)           // 48

// Scratch (static __device__ — no allocation).
__device__ __nv_bfloat16 g_A[(size_t)BATCH * KA];    // ~50 MB (L2-resident)
__device__ __nv_bfloat16 g_B[(size_t)OUT_DIM * KB];  // ~4.7 MB

// ===========================================================================
// Kernel 1 (fused): blocks 0..4095 -> A_cat prep; blocks 4096..4351 ->
// B_cat prep + zero out (so GEMM epilogues can RED-accumulate).
// ===========================================================================
__global__ void __launch_bounds__(256) prep_all(const float* __restrict__ x,
                                                const float* __restrict__ cp,
                                                const float* __restrict__ sc,
                                                float* __restrict__ out) {
    __shared__ uint32_t st[3072];                 // 12 KB row image (prep_a only)
    int blk = blockIdx.x;
    int i   = threadIdx.x;

    if (blk < BATCH) {
        // ---- prep_a: dense 12-wide basis/silu, split hi|lo bf16 ----
        int b = blk;
        float xv = x[(size_t)b * IN_DIM + i];
        float t8 = xv * 8.0f;
        float fl = floorf(t8);
        float u  = t8 - fl;
        int k0l = min(max((int)fl, 0), 7);
        const float inv6 = 1.0f / 6.0f;
        float u2 = u * u, u3 = u2 * u;
        float omu = 1.0f - u;
        float d[NROWS];
#pragma unroll
        for (int kk = 0; kk < NROWS; kk++) d[kk] = 0.0f;
        d[k0l + 0] = omu * omu * omu * inv6;
        d[k0l + 1] = (3.0f * u3 - 6.0f * u2 + 4.0f) * inv6;
        d[k0l + 2] = (-3.0f * u3 + 3.0f * u2 + 3.0f * u + 1.0f) * inv6;
        d[k0l + 3] = u3 * inv6;
        d[11]      = xv / (1.0f + __expf(-xv));   // silu (fast exp; err ~2^-17)

        unsigned short hb[NROWS], lb[NROWS];
#pragma unroll
        for (int kk = 0; kk < NROWS; kk++) {
            float v = d[kk];
            __nv_bfloat16 h = __float2bfloat16(v);
            float lo = v - __bfloat162float(h);
            __nv_bfloat16 l = __float2bfloat16(lo);
            hb[kk] = *reinterpret_cast<unsigned short*>(&h);
            lb[kk] = *reinterpret_cast<unsigned short*>(&l);
        }
#pragma unroll
        for (int j = 0; j < 6; j++) {
            st[i * 6 + j]        = (uint32_t)hb[2*j] | ((uint32_t)hb[2*j+1] << 16);
            st[1536 + i * 6 + j] = (uint32_t)lb[2*j] | ((uint32_t)lb[2*j+1] << 16);
        }
        __syncthreads();

        const uint4* s4 = reinterpret_cast<const uint4*>(st);
        uint4* g4 = reinterpret_cast<uint4*>(g_A) + (size_t)b * 768;
#pragma unroll
        for (int p = 0; p < 3; p++)
            g4[p * 256 + i] = s4[p * 256 + i];
    } else {
        // ---- prep_b: W split Whi|Wlo|Whi + zero out ----
        int o = blk - BATCH;
        float s = sc[i * OUT_DIM + o];
        const float* cpp = cp + (size_t)(i * OUT_DIM + o) * 19;
        __nv_bfloat16* pb = g_B + (size_t)o * KB + i * NROWS;
#pragma unroll
        for (int kk = 0; kk < NROWS; kk++) {
            float w = (kk < 11) ? s * cpp[kk + 8] : s;
            __nv_bfloat16 h = __float2bfloat16(w);
            float lo = w - __bfloat162float(h);
            pb[kk]            = h;
            pb[KSEG + kk]     = __float2bfloat16(lo);
            pb[2 * KSEG + kk] = h;
        }
        // zero out: 65536 threads x 4 float4 = 4 MB
        float4* o4 = reinterpret_cast<float4*>(out);
        int gt = o * 256 + i;
        const float4 z = make_float4(0.f, 0.f, 0.f, 0.f);
#pragma unroll
        for (int p = 0; p < 4; p++)
            o4[gt + 65536 * p] = z;
    }
}

// ===========================================================================
// PTX helpers (sm_80-class only: cp.async, ldmatrix, mma.sync — no tcgen05)
// ===========================================================================
__device__ __forceinline__ uint32_t smem_u32(const void* p) {
    uint32_t a;
    asm("{ .reg .u64 t; cvta.to.shared.u64 t, %1; cvt.u32.u64 %0, t; }"
        : "=r"(a) : "l"(p));
    return a;
}
__device__ __forceinline__ void cp16(uint32_t dst, const void* src) {
    asm volatile("cp.async.cg.shared.global [%0], [%1], 16;"
                 :: "r"(dst), "l"(src) : "memory");
}
__device__ __forceinline__ void cp_commit() {
    asm volatile("cp.async.commit_group;" ::: "memory");
}
template <int N>
__device__ __forceinline__ void cp_wait() {
    asm volatile("cp.async.wait_group %0;" :: "n"(N) : "memory");
}
__device__ __forceinline__ void ldm_x4(uint32_t* r, uint32_t addr) {
    asm volatile("ldmatrix.sync.aligned.m8n8.x4.shared.b16 {%0,%1,%2,%3}, [%4];"
                 : "=r"(r[0]), "=r"(r[1]), "=r"(r[2]), "=r"(r[3]) : "r"(addr));
}
__device__ __forceinline__ void mma16816(float* d, const uint32_t* a,
                                         const uint32_t* b) {
    asm volatile(
        "mma.sync.aligned.m16n8k16.row.col.f32.bf16.bf16.f32 "
        "{%0,%1,%2,%3}, {%4,%5,%6,%7}, {%8,%9}, {%0,%1,%2,%3};"
        : "+f"(d[0]), "+f"(d[1]), "+f"(d[2]), "+f"(d[3])
        : "r"(a[0]), "r"(a[1]), "r"(a[2]), "r"(a[3]), "r"(b[0]), "r"(b[1]));
}
__device__ __forceinline__ void redg_add(float* addr, float v) {
    asm volatile("red.global.add.f32 [%0], %1;" :: "l"(addr), "f"(v) : "memory");
}

// ===========================================================================
// Kernel 2: HMMA GEMM, split-K(2), RED-accumulating epilogue.
// CTA: M=128, N=64, K-half 4608. grid = 32 btile x 4 ntile x 2 khalf = 256
// CTAs, 256 threads, 8 warps 4(M)x2(N), warp tile 32x32.
// KC=64 (4 k-steps), ROWB=144, FOUR cp.async stages (110.6 KB smem ->
// TWO CTAs co-resident per SM). Both K-halves red.global.add into zeroed out
// (exact: two-operand IEEE add is order-independent -> deterministic).
// ===========================================================================
#define ROWB  144                       // bytes per padded smem row (128 data)
#define ASTG  (128 * ROWB)              // 18432
#define BSTG  (64 * ROWB)               // 9216
#define STG_B (ASTG + BSTG)             // 27648 per stage
#define NSTG  4
#define SMTOT (NSTG * STG_B)            // 110592 (x2 CTAs = 221 KB < 227 KB)

__global__ void __launch_bounds__(256) kan_mma(float* __restrict__ out) {
    extern __shared__ char smem[];
    uint32_t sbase = smem_u32(smem);
    uint32_t sA[NSTG], sB[NSTG];
#pragma unroll
    for (int s = 0; s < NSTG; s++) {
        sA[s] = sbase + s * STG_B;
        sB[s] = sbase + s * STG_B + ASTG;
    }

    int tid  = threadIdx.x;
    int wid  = tid >> 5;
    int lane = tid & 31;
    int btile  = blockIdx.x >> 3;         // 0..31
    int ntile  = (blockIdx.x >> 1) & 3;   // 0..3
    int khalf  = blockIdx.x & 1;          // 0..1
    int cbase  = khalf * NCHL;            // global chunk offset
    int warp_m = wid >> 1;                // 0..3
    int warp_n = wid & 1;                 // 0..1

    // ---- cp.async per-thread mapping (A: 4 ops, B: 2 ops per chunk) ----
    int u    = tid & 7;                   // 16B unit in 128B row
    int row0 = tid >> 3;                  // 0..31
    const __nv_bfloat16* gA[4];
    uint32_t dA[4];
#pragma unroll
    for (int j = 0; j < 4; j++) {
        int r = row0 + 32 * j;
        gA[j] = g_A + (size_t)(btile * 128 + r) * KA + u * 8;
        dA[j] = r * ROWB + u * 16;
    }
    const __nv_bfloat16* gB[2];
    uint32_t dB[2];
#pragma unroll
    for (int j = 0; j < 2; j++) {
        int r = row0 + 32 * j;
        gB[j] = g_B + (size_t)(ntile * 64 + r) * KB + u * 8;
        dB[j] = r * ROWB + u * 16;
    }

    // ---- ldmatrix per-lane base offsets ----
    uint32_t a_off[2];
#pragma unroll
    for (int mt = 0; mt < 2; mt++) {
        int r = warp_m * 32 + mt * 16 + (lane & 7) + 8 * ((lane >> 3) & 1);
        a_off[mt] = r * ROWB + (lane >> 4) * 16;
    }
    uint32_t b_off[2];
#pragma unroll
    for (int np = 0; np < 2; np++) {
        int r = warp_n * 32 + np * 16 + ((lane >> 4) & 1) * 8 + (lane & 7);
        b_off[np] = r * ROWB + ((lane >> 3) & 1) * 16;
    }

    float acc[2][4][4];
#pragma unroll
    for (int mt = 0; mt < 2; mt++)
#pragma unroll
        for (int nt = 0; nt < 4; nt++)
#pragma unroll
            for (int q = 0; q < 4; q++) acc[mt][nt][q] = 0.0f;

#define ISSUE(cl, s) do {                                                       \
        int _g = cbase + (cl);                    /* global chunk */            \
        int _seg = _g / CSEG;                                                   \
        int _aoff = ((_seg == 2) ? KSEG : 0) + (_g - _seg * CSEG) * KC;         \
        int _boff = _g * KC;                                                    \
        _Pragma("unroll")                                                       \
        for (int j = 0; j < 4; j++)                                             \
            cp16(sA[s] + dA[j], gA[j] + _aoff);                                 \
        _Pragma("unroll")                                                       \
        for (int j = 0; j < 2; j++)                                             \
            cp16(sB[s] + dB[j], gB[j] + _boff);                                 \
        cp_commit();                                                            \
    } while (0)

#define LOADF(buf, s, ks) do {                                                  \
        uint32_t _kb = (ks) * 32;                                               \
        _Pragma("unroll")                                                       \
        for (int mt = 0; mt < 2; mt++)                                          \
            ldm_x4(afr[buf][mt], sA[s] + a_off[mt] + _kb);                      \
        _Pragma("unroll")                                                       \
        for (int np = 0; np < 2; np++)                                          \
            ldm_x4(bfr[buf][np], sB[s] + b_off[np] + _kb);                      \
    } while (0)

#define MMAS(buf) do {                                                          \
        _Pragma("unroll")                                                       \
        for (int mt = 0; mt < 2; mt++) {                                        \
            _Pragma("unroll")                                                   \
            for (int nt = 0; nt < 4; nt++) {                                    \
                uint32_t bb[2] = { bfr[buf][nt >> 1][(nt & 1) * 2 + 0],         \
                                   bfr[buf][nt >> 1][(nt & 1) * 2 + 1] };       \
                mma16816(acc[mt][nt], afr[buf][mt], bb);                        \
            }                                                                   \
        }                                                                       \
    } while (0)

    // prologue: 3 chunks in flight
    ISSUE(0, 0);
    ISSUE(1, 1);
    ISSUE(2, 2);

    for (int c = 0; c < NCHL; c++) {
        int s = c % NSTG;
        if (c + 2 < NCHL)      cp_wait<2>();
        else if (c + 1 < NCHL) cp_wait<1>();
        else                   cp_wait<0>();
        __syncthreads();

        if (c + 3 < NCHL) ISSUE(c + 3, (c + 3) % NSTG);  // stage freed at c-1

        uint32_t afr[2][2][4], bfr[2][2][4];
        LOADF(0, s, 0);
#pragma unroll
        for (int ks = 0; ks < 4; ks++) {
            if (ks < 3) LOADF((ks + 1) & 1, s, ks + 1);
            MMAS(ks & 1);
        }
    }

    // ---- epilogue: both K-halves RED-accumulate into zeroed out ----
    int mg = btile * 128 + warp_m * 32 + (lane >> 2);
    int ng = ntile * 64 + warp_n * 32 + (lane & 3) * 2;
#pragma unroll
    for (int mt = 0; mt < 2; mt++) {
#pragma unroll
        for (int nt = 0; nt < 4; nt++) {
            int m0 = mg + mt * 16;
            int n0 = ng + nt * 8;
            float* p0 = out + (size_t)m0 * OUT_DIM + n0;
            float* p1 = out + (size_t)(m0 + 8) * OUT_DIM + n0;
            redg_add(p0,     acc[mt][nt][0]);
            redg_add(p0 + 1, acc[mt][nt][1]);
            redg_add(p1,     acc[mt][nt][2]);
            redg_add(p1 + 1, acc[mt][nt][3]);
        }
    }
#undef MMAS
#undef LOADF
#undef ISSUE
}

// ---------------------------------------------------------------------------
extern "C" void kernel_launch(void* const* d_in, const int* in_sizes, int n_in,
                              void* d_out, int out_size) {
    const float* x  = (const float*)d_in[0];   // [4096, 256]
    const float* cp = (const float*)d_in[1];   // [256, 256, 19]
    const float* sc = (const float*)d_in[2];   // [256, 256]
    float* out = (float*)d_out;                // [4096, 256]

    cudaFuncSetAttribute(kan_mma, cudaFuncAttributeMaxDynamicSharedMemorySize,
                         SMTOT);

    prep_all<<<BATCH + OUT_DIM, 256>>>(x, cp, sc, out);
    kan_mma<<<256, 256, SMTOT>>>(out);
}